// round 16
// baseline (speedup 1.0000x reference)
#include <cuda_runtime.h>
#include <cuda_bf16.h>

// Floor-family probe: QPT=8 at TPB=256 (the one untested cell in the sweep).
//
// Established floor model (9 runs at 49.7-50.9us kernel): LTS aggregate binds
// — 218MB compulsory reads + ~410MB slice-internal atomic RMW at the
// ~6300 B/cyc path-independent cap. QPT=1 and QPT=4 both sit on the floor;
// QPT=8 halves the grid (6250 blocks -> less launch/drain + tail imbalance)
// and deepens per-warp MLP to 16, at bounded risk of L1tex-queue contention
// (block shape unchanged at 8 warps; regs stay < 64).
//
// Addressing invariant (proven): warp loads 32 consecutive float4s = 4 x
// 128B lines per LDG.128; 4 lanes share one broadcast src int; each edge's
// 4 RED.E.ADD.F32.V4 lanes cover one contiguous 64B output line. edge_w
// streams evict-first (__ldcs); the 6.4MB destination stays L2-resident.
//
// Fixed sizes: E = 3,200,000, F = 16 -> 12.8M quads = 1.6M threads x 8.

#define E_TOTAL   3200000
#define NUM_QUADS (E_TOTAL * 4)
#define TPB       256
#define QPT       8
#define TOTAL_THREADS (NUM_QUADS / QPT)        // 1,600,000
#define NBLK          (TOTAL_THREADS / TPB)    // 6,250

__global__ void __launch_bounds__(TPB)
spmm_scatter_kernel(const int* __restrict__ src,
                    const float4* __restrict__ w4,   // [E*4] float4
                    float4* __restrict__ out4)       // [N*4] float4
{
    const int tid = blockIdx.x * TPB + threadIdx.x;
    const int S   = TOTAL_THREADS;

    int    idx[QPT];
    int    s[QPT];
    float4 v[QPT];

    // Front-batched independent loads (MLP_p1 ~ 16).
#pragma unroll
    for (int k = 0; k < QPT; k++) {
        idx[k] = tid + k * S;
        s[k]   = __ldg(&src[idx[k] >> 2]);
    }
#pragma unroll
    for (int k = 0; k < QPT; k++)
        v[k] = __ldcs(&w4[idx[k]]);   // evict-first: edge_w streams once

    // Fire-and-forget vector reduction atomics.
#pragma unroll
    for (int k = 0; k < QPT; k++)
        atomicAdd(&out4[((size_t)s[k] << 2) + (idx[k] & 3)], v[k]);
}

extern "C" void kernel_launch(void* const* d_in, const int* in_sizes, int n_in,
                              void* d_out, int out_size)
{
    const int*   edge   = (const int*)d_in[0];   // edge[0] = src, first E ints
    const float* edge_w = (const float*)d_in[1];

    // d_out poisoned to 0xAA -> zero it (memset node is graph-capturable);
    // also pre-warms the 6.4 MB destination region in L2. Mandatory every
    // replay: REDs accumulate otherwise.
    cudaMemsetAsync(d_out, 0, (size_t)out_size * sizeof(float), 0);

    spmm_scatter_kernel<<<NBLK, TPB>>>(
        edge,
        (const float4*)edge_w,
        (float4*)d_out);
}